// round 3
// baseline (speedup 1.0000x reference)
#include <cuda_runtime.h>
#include <cstdint>

#define TT  256
#define BB  256
#define NIN 512
#define H1V 512
#define H2V 512
#define ON  128

// ---------------- device scratch (static, no allocation) ----------------
__device__ float        g_W1qT[NIN * H1V];          // [i][j] fp32 quantized W1 (transposed)
__device__ signed char  g_W2cm[H1V * H2V];          // [i][j] = q(W2[j,i])
__device__ signed char  g_Wrcm[H2V * H2V];          // [i][j] = q(Wrec[j,i])
__device__ signed char  g_W3cm[H2V * ON];           // [i][o] = q(W3[o,i])
__device__ float        g_scales[4];
__device__ unsigned int g_absmax[4];
__device__ float        g_cur1[(size_t)TT * BB * H1V];   // [(b*256+t)][j]  (~134MB)
__device__ unsigned int g_s1w[TT * BB * 16];             // spike bitmask [(b*256+t)][word]

__device__ __forceinline__ float clip01(float x) { return fminf(fmaxf(x, 0.f), 1.f); }

// ---------------- quantization ----------------
__global__ void k_zero() {
    if (threadIdx.x < 4) g_absmax[threadIdx.x] = 0u;
}

__global__ void k_absmax(const float* __restrict__ src, int n, int slot) {
    float v = 0.f;
    for (int i = blockIdx.x * blockDim.x + threadIdx.x; i < n; i += gridDim.x * blockDim.x)
        v = fmaxf(v, fabsf(src[i]));
    #pragma unroll
    for (int o = 16; o; o >>= 1) v = fmaxf(v, __shfl_xor_sync(0xffffffffu, v, o));
    __shared__ float sm[8];
    if ((threadIdx.x & 31) == 0) sm[threadIdx.x >> 5] = v;
    __syncthreads();
    if (threadIdx.x == 0) {
        float m = sm[0];
        #pragma unroll
        for (int w = 1; w < 8; w++) m = fmaxf(m, sm[w]);
        atomicMax(&g_absmax[slot], __float_as_uint(m));
    }
}

__global__ void k_scales() {
    if (threadIdx.x < 4)
        g_scales[threadIdx.x] = __uint_as_float(g_absmax[threadIdx.x]) / 127.0f;
}

__global__ void k_quantW1(const float* __restrict__ W1) {
    int tid = blockIdx.x * blockDim.x + threadIdx.x;   // 262144
    float s = g_scales[0];
    int i = tid >> 9, j = tid & 511;
    float w = W1[j * 512 + i];
    float q = fminf(fmaxf(rintf(w / s), -127.f), 127.f);
    g_W1qT[tid] = q * s;
}

// which: 1 -> W2, 2 -> Wrec, 3 -> W3
__global__ void k_quant_cm(const float* __restrict__ W, int which) {
    int tid = blockIdx.x * blockDim.x + threadIdx.x;
    signed char* dst = (which == 1) ? g_W2cm : (which == 2) ? g_Wrcm : g_W3cm;
    int rl = (which == 3) ? 7 : 9;                     // log2(rows)
    float s = g_scales[which];
    int i = tid >> rl;
    int j = tid & ((1 << rl) - 1);
    float w = W[j * 512 + i];
    float q = fminf(fmaxf(rintf(w / s), -127.f), 127.f);
    dst[tid] = (signed char)(int)q;
}

// ---------------- layer-1 GEMM: cur1[(b*256+t)][j] = sum_i data[b,i,t] * W1q[j,i] ----------------
__global__ __launch_bounds__(256) void k_gemm1(const float* __restrict__ data) {
    __shared__ float As[16][128];
    __shared__ float Bs[16][128];
    const int lt = threadIdx.x;
    const int m0 = blockIdx.x << 7;
    const int n0 = blockIdx.y << 7;
    const int b  = m0 >> 8;
    const int tb = m0 & 255;
    const float* Ab = data + (size_t)b * (NIN * TT) + tb;   // A[mi,i] = Ab[i*256 + mi]
    const int tx = lt & 15, ty = lt >> 4;

    float acc[8][8];
    #pragma unroll
    for (int u = 0; u < 8; u++)
        #pragma unroll
        for (int v = 0; v < 8; v++) acc[u][v] = 0.f;

    for (int k0 = 0; k0 < 512; k0 += 16) {
        #pragma unroll
        for (int r = 0; r < 8; r++) {
            int idx = lt + (r << 8);
            int mi = idx & 127, ki = idx >> 7;
            As[ki][mi] = Ab[(k0 + ki) * TT + mi];
            Bs[ki][mi] = g_W1qT[(k0 + ki) * H1V + n0 + mi];
        }
        __syncthreads();
        #pragma unroll
        for (int k = 0; k < 16; k++) {
            const float4* pa = reinterpret_cast<const float4*>(&As[k][ty << 3]);
            const float4* pb = reinterpret_cast<const float4*>(&Bs[k][tx << 3]);
            float4 a0 = pa[0], a1 = pa[1], b0 = pb[0], b1 = pb[1];
            float a[8] = {a0.x, a0.y, a0.z, a0.w, a1.x, a1.y, a1.z, a1.w};
            float bv[8] = {b0.x, b0.y, b0.z, b0.w, b1.x, b1.y, b1.z, b1.w};
            #pragma unroll
            for (int u = 0; u < 8; u++)
                #pragma unroll
                for (int v = 0; v < 8; v++)
                    acc[u][v] = fmaf(a[u], bv[v], acc[u][v]);
        }
        __syncthreads();
    }
    #pragma unroll
    for (int u = 0; u < 8; u++) {
        float* C = g_cur1 + (size_t)(m0 + (ty << 3) + u) * H1V + n0 + (tx << 3);
        reinterpret_cast<float4*>(C)[0] = make_float4(acc[u][0], acc[u][1], acc[u][2], acc[u][3]);
        reinterpret_cast<float4*>(C)[1] = make_float4(acc[u][4], acc[u][5], acc[u][6], acc[u][7]);
    }
}

// ---------------- layer-1 membrane scan -> spike bitmask ----------------
__global__ void k_scan1(const float* __restrict__ beta1p, const float* __restrict__ th1p) {
    int tid = blockIdx.x * blockDim.x + threadIdx.x;   // 131072
    int b = tid >> 9, j = tid & 511;
    float b1 = clip01(*beta1p);
    float th = *th1p;
    float m = 0.f;
    const float* cur = g_cur1 + (size_t)b * (256 * 512) + j;
    unsigned wslot = (unsigned)(j >> 5);
    unsigned* s1out = g_s1w + (size_t)b * (256 * 16) + wslot;
    for (int t = 0; t < 256; t++) {
        float c = cur[t * 512];
        m = b1 * m + c;
        bool s = (m - th) > 0.0f;
        if (s) m = 0.f;
        unsigned mask = __ballot_sync(0xffffffffu, s);
        if ((threadIdx.x & 31) == 0) s1out[t * 16] = mask;
    }
}

// ---------------- persistent recurrent + output layers: one CTA per batch row ----------------
__global__ __launch_bounds__(512) void k_phaseB(
    const float* __restrict__ brp, const float* __restrict__ thrp,
    const float* __restrict__ b2p, const float* __restrict__ th2p,
    float* __restrict__ out)
{
    const int b    = blockIdx.x;
    const int tid  = threadIdx.x;
    const int q    = tid >> 7;       // quad 0..3
    const int r    = tid & 127;      // lane within quad -> owns j = 4r..4r+3 during gather
    const int wid  = tid >> 5, lane = tid & 31;
    const unsigned lmask = (1u << lane) - 1u;

    __shared__ unsigned short list1[512], listR[512], listO[512];
    __shared__ int cnt1[16], cntR[16], cntO[16];
    __shared__ int sacc2[4][512];
    __shared__ int saccR[4][512];
    __shared__ int sacc3[4][128];

    const float br  = clip01(*brp),  thr = *thrp;
    const float b2  = clip01(*b2p),  th2 = *th2p;
    const float sc2 = g_scales[1], scr = g_scales[2], sc3 = g_scales[3];

    float mr = 0.f, m2 = 0.f;
    int srj = 0;

    const unsigned* s1base = g_s1w + (size_t)b * (256 * 16);
    const int* W2i = reinterpret_cast<const int*>(g_W2cm);
    const int* Wri = reinterpret_cast<const int*>(g_Wrcm);

    for (int t = 0; t < 256; t++) {
        unsigned wbits = s1base[t * 16 + wid];
        int s1j = (wbits >> lane) & 1;

        unsigned msk1 = __ballot_sync(0xffffffffu, s1j);
        unsigned mskR = __ballot_sync(0xffffffffu, srj);
        if (lane == 0) { cnt1[wid] = __popc(msk1); cntR[wid] = __popc(mskR); }
        __syncthreads();

        int off1 = 0, offR = 0, n1 = 0, nR = 0;
        #pragma unroll
        for (int w = 0; w < 16; w++) {
            int c1 = cnt1[w], cR = cntR[w];
            if (w < wid) { off1 += c1; offR += cR; }
            n1 += c1; nR += cR;
        }
        if (s1j) list1[off1 + __popc(msk1 & lmask)] = (unsigned short)tid;
        if (srj) listR[offR + __popc(mskR & lmask)] = (unsigned short)tid;
        __syncthreads();

        // sparse integer column gathers (exact): quad q takes k = q, q+4, ...
        int a20 = 0, a21 = 0, a22 = 0, a23 = 0;
        for (int k = q; k < n1; k += 4) {
            int i = list1[k];
            int w = __ldg(W2i + i * 128 + r);
            a20 += (int)(signed char)(w);
            a21 += (int)(signed char)(w >> 8);
            a22 += (int)(signed char)(w >> 16);
            a23 += (w >> 24);
        }
        int aR0 = 0, aR1 = 0, aR2 = 0, aR3 = 0;
        for (int k = q; k < nR; k += 4) {
            int i = listR[k];
            int w = __ldg(Wri + i * 128 + r);
            aR0 += (int)(signed char)(w);
            aR1 += (int)(signed char)(w >> 8);
            aR2 += (int)(signed char)(w >> 16);
            aR3 += (w >> 24);
        }
        int jb = r << 2;
        *reinterpret_cast<int4*>(&sacc2[q][jb]) = make_int4(a20, a21, a22, a23);
        *reinterpret_cast<int4*>(&saccR[q][jb]) = make_int4(aR0, aR1, aR2, aR3);
        __syncthreads();

        int A2 = sacc2[0][tid] + sacc2[1][tid] + sacc2[2][tid] + sacc2[3][tid];
        int AR = saccR[0][tid] + saccR[1][tid] + saccR[2][tid] + saccR[3][tid];
        float h  = sc2 * (float)A2 + scr * (float)AR;
        float um = br * mr + h;
        mr = um * (1.f - (float)srj);                  // reset_delay: uses OLD sr
        int srn = (mr - thr) > 0.f ? 1 : 0;

        unsigned mskO = __ballot_sync(0xffffffffu, srn);
        if (lane == 0) cntO[wid] = __popc(mskO);
        __syncthreads();
        int offO = 0, nO = 0;
        #pragma unroll
        for (int w = 0; w < 16; w++) { int c = cntO[w]; if (w < wid) offO += c; nO += c; }
        if (srn) listO[offO + __popc(mskO & lmask)] = (unsigned short)tid;
        __syncthreads();

        int a3 = 0;
        for (int k = q; k < nO; k += 4) {
            int i = listO[k];
            a3 += (int)g_W3cm[i * 128 + r];
        }
        sacc3[q][r] = a3;
        __syncthreads();

        if (tid < 128) {
            int A3 = sacc3[0][tid] + sacc3[1][tid] + sacc3[2][tid] + sacc3[3][tid];
            m2 = b2 * m2 + sc3 * (float)A3;
            int s2 = (m2 - th2) > 0.f ? 1 : 0;
            if (s2) m2 = 0.f;
            out[((size_t)t * BB + b) * ON + tid] = (float)s2;
        }
        srj = srn;
        __syncthreads();
    }
}

// ---------------- launch ----------------
extern "C" void kernel_launch(void* const* d_in, const int* in_sizes, int n_in,
                              void* d_out, int out_size) {
    const float* data  = (const float*)d_in[0];
    const float* W1    = (const float*)d_in[1];
    const float* W2    = (const float*)d_in[2];
    const float* Wr    = (const float*)d_in[3];
    const float* W3    = (const float*)d_in[4];
    const float* beta1 = (const float*)d_in[5];
    const float* th1   = (const float*)d_in[6];
    const float* betar = (const float*)d_in[7];
    const float* thr   = (const float*)d_in[8];
    const float* beta2 = (const float*)d_in[9];
    const float* th2   = (const float*)d_in[10];
    float* out = (float*)d_out;

    k_zero<<<1, 32>>>();
    k_absmax<<<64, 256>>>(W1, 512 * 512, 0);
    k_absmax<<<64, 256>>>(W2, 512 * 512, 1);
    k_absmax<<<64, 256>>>(Wr, 512 * 512, 2);
    k_absmax<<<64, 256>>>(W3, 128 * 512, 3);
    k_scales<<<1, 4>>>();
    k_quantW1<<<512, 512>>>(W1);
    k_quant_cm<<<512, 512>>>(W2, 1);
    k_quant_cm<<<512, 512>>>(Wr, 2);
    k_quant_cm<<<128, 512>>>(W3, 3);

    dim3 ggrid(512, 4);
    k_gemm1<<<ggrid, 256>>>(data);
    k_scan1<<<512, 256>>>(beta1, th1);
    k_phaseB<<<256, 512>>>(betar, thr, beta2, th2, out);
}

// round 6
// speedup vs baseline: 1.3472x; 1.3472x over previous
#include <cuda_runtime.h>
#include <cuda_fp16.h>
#include <cstdint>

#define TT  256
#define BB  256
#define NIN 512
#define H1V 512
#define H2V 512
#define ON  128

// ---------------- device scratch (static, no allocation) ----------------
__device__ float        g_W1qT[NIN * H1V];          // [i][j] fp32 quantized W1 (transposed)
__device__ __half       g_W2h[H1V * H2V];           // [i][j] = q(W2[j,i]) exact int in fp16
__device__ signed char  g_Wrcm[H2V * H2V];          // [i][j] = q(Wrec[j,i])
__device__ signed char  g_W3cm[H2V * ON];           // [i][o] = q(W3[o,i])
__device__ float        g_scales[4];
__device__ unsigned int g_absmax[4];
__device__ float        g_cur1[(size_t)TT * BB * H1V];   // phase A currents, then reused as C2
__device__ unsigned int g_s1w[TT * BB * 16];             // layer-1 spike bitmask

__device__ __forceinline__ float clip01(float x) { return fminf(fmaxf(x, 0.f), 1.f); }

__device__ __forceinline__ unsigned smem_u32(const void* p) {
    return (unsigned)__cvta_generic_to_shared(p);
}

// ---- packed fp32x2 helpers (SASS FFMA2; per-lane RN fp32, bit-identical) ----
__device__ __forceinline__ unsigned long long pk2(float lo, float hi) {
    unsigned long long r;
    asm("mov.b64 %0, {%1,%2};" : "=l"(r) : "f"(lo), "f"(hi));
    return r;
}
__device__ __forceinline__ void fma2(unsigned long long& d, unsigned long long a,
                                     unsigned long long b) {
    asm("fma.rn.f32x2 %0, %1, %2, %0;" : "+l"(d) : "l"(a), "l"(b));
}
__device__ __forceinline__ float2 upk2(unsigned long long v) {
    float2 f;
    asm("mov.b64 {%0,%1}, %2;" : "=f"(f.x), "=f"(f.y) : "l"(v));
    return f;
}

// ---- ldmatrix / mma helpers (used only by exact-integer gemm2) ----
__device__ __forceinline__ void ldmx4t(unsigned& r0, unsigned& r1, unsigned& r2, unsigned& r3,
                                       unsigned addr) {
    asm volatile("ldmatrix.sync.aligned.m8n8.x4.trans.shared.b16 {%0,%1,%2,%3}, [%4];"
                 : "=r"(r0), "=r"(r1), "=r"(r2), "=r"(r3) : "r"(addr));
}
__device__ __forceinline__ void mma16816(float* d, const unsigned* a, const unsigned* b) {
    asm volatile(
        "mma.sync.aligned.m16n8k16.row.col.f32.f16.f16.f32 "
        "{%0,%1,%2,%3}, {%4,%5,%6,%7}, {%8,%9}, {%0,%1,%2,%3};"
        : "+f"(d[0]), "+f"(d[1]), "+f"(d[2]), "+f"(d[3])
        : "r"(a[0]), "r"(a[1]), "r"(a[2]), "r"(a[3]), "r"(b[0]), "r"(b[1]));
}
__device__ __forceinline__ unsigned addrA(unsigned base, int lane, int k16, int col) {
    int g = lane >> 3, rig = lane & 7;
    int krow = k16 + ((g & 2) ? 8 : 0) + rig;
    int c    = col + ((g & 1) ? 8 : 0);
    return base + (unsigned)((krow * 136 + c) * 2);
}
__device__ __forceinline__ unsigned addrB(unsigned base, int lane, int k16, int col) {
    int g = lane >> 3, rig = lane & 7;
    int krow = k16 + ((g & 1) ? 8 : 0) + rig;
    int c    = col + ((g & 2) ? 8 : 0);
    return base + (unsigned)((krow * 136 + c) * 2);
}

// ---------------- quantization ----------------
__global__ void k_zero() {
    if (threadIdx.x < 4) g_absmax[threadIdx.x] = 0u;
}

__global__ void k_absmax(const float* __restrict__ src, int n, int slot) {
    float v = 0.f;
    for (int i = blockIdx.x * blockDim.x + threadIdx.x; i < n; i += gridDim.x * blockDim.x)
        v = fmaxf(v, fabsf(src[i]));
    #pragma unroll
    for (int o = 16; o; o >>= 1) v = fmaxf(v, __shfl_xor_sync(0xffffffffu, v, o));
    __shared__ float sm[8];
    if ((threadIdx.x & 31) == 0) sm[threadIdx.x >> 5] = v;
    __syncthreads();
    if (threadIdx.x == 0) {
        float m = sm[0];
        #pragma unroll
        for (int w = 1; w < 8; w++) m = fmaxf(m, sm[w]);
        atomicMax(&g_absmax[slot], __float_as_uint(m));
    }
}

__global__ void k_scales() {
    if (threadIdx.x < 4)
        g_scales[threadIdx.x] = __uint_as_float(g_absmax[threadIdx.x]) / 127.0f;
}

__global__ void k_quantW1(const float* __restrict__ W1) {
    int tid = blockIdx.x * blockDim.x + threadIdx.x;   // 262144
    float s = g_scales[0];
    int i = tid >> 9, j = tid & 511;
    float w = W1[j * 512 + i];
    float q = fminf(fmaxf(rintf(w / s), -127.f), 127.f);
    g_W1qT[tid] = q * s;
}

__global__ void k_quantW2h(const float* __restrict__ W2) {
    int tid = blockIdx.x * blockDim.x + threadIdx.x;   // 262144
    float s = g_scales[1];
    int i = tid >> 9, j = tid & 511;
    float w = W2[j * 512 + i];
    float q = fminf(fmaxf(rintf(w / s), -127.f), 127.f);
    g_W2h[tid] = __float2half_rn(q);                   // exact integer in fp16
}

// which: 2 -> Wrec, 3 -> W3  (int8 col-major)
__global__ void k_quant_cm(const float* __restrict__ W, int which) {
    int tid = blockIdx.x * blockDim.x + threadIdx.x;
    signed char* dst = (which == 2) ? g_Wrcm : g_W3cm;
    int rl = (which == 3) ? 7 : 9;
    float s = g_scales[which];
    int i = tid >> rl;
    int j = tid & ((1 << rl) - 1);
    float w = W[j * 512 + i];
    float q = fminf(fmaxf(rintf(w / s), -127.f), 127.f);
    dst[tid] = (signed char)(int)q;
}

// ---------------- layer-1 GEMM: bit-identical to R1 arithmetic, FFMA2 packed ----------------
// cur1[(b*256+t)][j] = sum_i data[b,i,t] * W1q[j,i], strictly ascending k per output
__global__ __launch_bounds__(256, 2) void k_gemm1(const float* __restrict__ data) {
    __shared__ float As[16][128];
    __shared__ float Bs[16][128];
    const int lt = threadIdx.x;
    const int m0 = blockIdx.x << 7;
    const int n0 = blockIdx.y << 7;
    const int b  = m0 >> 8;
    const int tb = m0 & 255;
    const float* Ab = data + (size_t)b * (NIN * TT) + tb;   // A[mi,i] = Ab[i*256 + mi]
    const int tx = lt & 15, ty = lt >> 4;

    unsigned long long acc2[8][4];    // [u][vpair] packed (v even, v odd)
    #pragma unroll
    for (int u = 0; u < 8; u++)
        #pragma unroll
        for (int vp = 0; vp < 4; vp++) acc2[u][vp] = 0ull;

    for (int k0 = 0; k0 < 512; k0 += 16) {
        #pragma unroll
        for (int r = 0; r < 8; r++) {
            int idx = lt + (r << 8);
            int mi = idx & 127, ki = idx >> 7;
            As[ki][mi] = Ab[(k0 + ki) * TT + mi];
            Bs[ki][mi] = g_W1qT[(k0 + ki) * H1V + n0 + mi];
        }
        __syncthreads();
        #pragma unroll
        for (int k = 0; k < 16; k++) {
            const float4* pa = reinterpret_cast<const float4*>(&As[k][ty << 3]);
            const float4* pb = reinterpret_cast<const float4*>(&Bs[k][tx << 3]);
            float4 a0 = pa[0], a1 = pa[1], b0 = pb[0], b1 = pb[1];
            float a[8] = {a0.x, a0.y, a0.z, a0.w, a1.x, a1.y, a1.z, a1.w};
            unsigned long long bp[4] = {pk2(b0.x, b0.y), pk2(b0.z, b0.w),
                                        pk2(b1.x, b1.y), pk2(b1.z, b1.w)};
            #pragma unroll
            for (int u = 0; u < 8; u++) {
                unsigned long long aa = pk2(a[u], a[u]);
                fma2(acc2[u][0], aa, bp[0]);
                fma2(acc2[u][1], aa, bp[1]);
                fma2(acc2[u][2], aa, bp[2]);
                fma2(acc2[u][3], aa, bp[3]);
            }
        }
        __syncthreads();
    }
    #pragma unroll
    for (int u = 0; u < 8; u++) {
        float2 e0 = upk2(acc2[u][0]), e1 = upk2(acc2[u][1]);
        float2 e2 = upk2(acc2[u][2]), e3 = upk2(acc2[u][3]);
        float* C = g_cur1 + (size_t)(m0 + (ty << 3) + u) * H1V + n0 + (tx << 3);
        reinterpret_cast<float4*>(C)[0] = make_float4(e0.x, e0.y, e1.x, e1.y);
        reinterpret_cast<float4*>(C)[1] = make_float4(e2.x, e2.y, e3.x, e3.y);
    }
}

// ---------------- layer-1 membrane scan -> spike bitmask ----------------
__global__ void k_scan1(const float* __restrict__ beta1p, const float* __restrict__ th1p) {
    int tid = blockIdx.x * blockDim.x + threadIdx.x;   // 131072
    int b = tid >> 9, j = tid & 511;
    float b1 = clip01(*beta1p);
    float th = *th1p;
    float m = 0.f;
    const float* cur = g_cur1 + (size_t)b * (256 * 512) + j;
    unsigned wslot = (unsigned)(j >> 5);
    unsigned* s1out = g_s1w + (size_t)b * (256 * 16) + wslot;
    for (int t = 0; t < 256; t++) {
        float c = cur[t * 512];
        m = b1 * m + c;
        bool s = (m - th) > 0.0f;
        if (s) m = 0.f;
        unsigned mask = __ballot_sync(0xffffffffu, s);
        if ((threadIdx.x & 31) == 0) s1out[t * 16] = mask;
    }
}

// ---------------- batched s1 @ W2^T (binary A, exact int accumulation on TC) ----------------
// C2[m][j] = sum_i s1[m,i] * q2[j,i]   (exact integers -> stored as float, into g_cur1)
__global__ __launch_bounds__(256, 2) void k_gemm2_tc() {
    __shared__ __align__(16) __half Ahs[32 * 136];
    __shared__ __align__(16) __half Bh[32 * 136];
    __shared__ unsigned wbuf[128];
    const int tid = threadIdx.x, lane = tid & 31, wid = tid >> 5;
    const int wm = wid & 3, wn = wid >> 2;
    const int n0 = blockIdx.x << 7, m0 = blockIdx.y << 7;
    const int lk = tid >> 3;
    const int lm = (tid & 7) << 4;

    const unsigned baseA = smem_u32(&Ahs[0]);
    const unsigned baseB = smem_u32(&Bh[0]);

    float acc[2][8][4];
    #pragma unroll
    for (int mt = 0; mt < 2; mt++)
        #pragma unroll
        for (int nt = 0; nt < 8; nt++)
            #pragma unroll
            for (int e = 0; e < 4; e++) acc[mt][nt][e] = 0.f;

    const __half one = __float2half_rn(1.f);
    const __half zero = __float2half_rn(0.f);

    for (int k0 = 0; k0 < 512; k0 += 32) {
        __syncthreads();
        if (tid < 128)
            wbuf[tid] = g_s1w[(size_t)(m0 + tid) * 16 + (k0 >> 5)];
        {
            const __half* Bg = g_W2h + (size_t)(k0 + lk) * 512 + n0 + lm;
            *reinterpret_cast<int4*>(&Bh[lk * 136 + lm])     = *reinterpret_cast<const int4*>(Bg);
            *reinterpret_cast<int4*>(&Bh[lk * 136 + lm + 8]) = *reinterpret_cast<const int4*>(Bg + 8);
        }
        __syncthreads();
        #pragma unroll
        for (int i = 0; i < 8; i++) {
            int m = lm + 2 * i;
            unsigned w0 = wbuf[m], w1 = wbuf[m + 1];
            __half v0 = ((w0 >> lk) & 1u) ? one : zero;
            __half v1 = ((w1 >> lk) & 1u) ? one : zero;
            *reinterpret_cast<__half2*>(&Ahs[lk * 136 + m]) = __halves2half2(v0, v1);
        }
        __syncthreads();

        #pragma unroll
        for (int kk = 0; kk < 2; kk++) {
            const int k16 = kk * 16;
            unsigned bf[8][2];
            #pragma unroll
            for (int p = 0; p < 4; p++) {
                unsigned r0, r1, r2, r3;
                ldmx4t(r0, r1, r2, r3, addrB(baseB, lane, k16, wn * 64 + p * 16));
                bf[2 * p][0] = r0; bf[2 * p][1] = r1;
                bf[2 * p + 1][0] = r2; bf[2 * p + 1][1] = r3;
            }
            #pragma unroll
            for (int mt = 0; mt < 2; mt++) {
                unsigned a[4];
                ldmx4t(a[0], a[1], a[2], a[3], addrA(baseA, lane, k16, wm * 32 + mt * 16));
                #pragma unroll
                for (int nt = 0; nt < 8; nt++)
                    mma16816(acc[mt][nt], a, bf[nt]);
            }
        }
    }

    const int rr = lane >> 2, cq = (lane & 3) * 2;
    #pragma unroll
    for (int mt = 0; mt < 2; mt++) {
        #pragma unroll
        for (int nt = 0; nt < 8; nt++) {
            int row0 = m0 + wm * 32 + mt * 16 + rr;
            int col  = n0 + wn * 64 + nt * 8 + cq;
            float2 v0 = make_float2(acc[mt][nt][0], acc[mt][nt][1]);
            float2 v1 = make_float2(acc[mt][nt][2], acc[mt][nt][3]);
            *reinterpret_cast<float2*>(&g_cur1[(size_t)row0 * 512 + col])       = v0;
            *reinterpret_cast<float2*>(&g_cur1[(size_t)(row0 + 8) * 512 + col]) = v1;
        }
    }
}

// ---------------- persistent recurrent + output layers: one CTA per batch row ----------------
__global__ __launch_bounds__(512) void k_phaseB(
    const float* __restrict__ brp, const float* __restrict__ thrp,
    const float* __restrict__ b2p, const float* __restrict__ th2p,
    float* __restrict__ out)
{
    const int b    = blockIdx.x;
    const int tid  = threadIdx.x;
    const int q    = tid >> 7;
    const int r    = tid & 127;
    const int wid  = tid >> 5, lane = tid & 31;
    const unsigned lmask = (1u << lane) - 1u;

    __shared__ unsigned short listR[512], listO[512];
    __shared__ int cntR[16], cntO[16];
    __shared__ int saccR[4][512];
    __shared__ int sacc3[4][128];

    const float br  = clip01(*brp),  thr = *thrp;
    const float b2  = clip01(*b2p),  th2 = *th2p;
    const float sc2 = g_scales[1], scr = g_scales[2], sc3 = g_scales[3];

    float mr = 0.f, m2 = 0.f;
    int srj = 0;

    const float* c2p = g_cur1 + (size_t)b * (256 * 512);
    const int* Wri = reinterpret_cast<const int*>(g_Wrcm);

    for (int t = 0; t < 256; t++) {
        float c2 = c2p[(size_t)t * 512 + tid];   // exact integer value of s1 @ W2q^T

        unsigned mskR = __ballot_sync(0xffffffffu, srj);
        if (lane == 0) cntR[wid] = __popc(mskR);
        __syncthreads();

        int offR = 0, nR = 0;
        #pragma unroll
        for (int w = 0; w < 16; w++) {
            int cR = cntR[w];
            if (w < wid) offR += cR;
            nR += cR;
        }
        if (srj) listR[offR + __popc(mskR & lmask)] = (unsigned short)tid;
        __syncthreads();

        int aR0 = 0, aR1 = 0, aR2 = 0, aR3 = 0;
        for (int k = q; k < nR; k += 4) {
            int i = listR[k];
            int w = __ldg(Wri + i * 128 + r);
            aR0 += (int)(signed char)(w);
            aR1 += (int)(signed char)(w >> 8);
            aR2 += (int)(signed char)(w >> 16);
            aR3 += (w >> 24);
        }
        *reinterpret_cast<int4*>(&saccR[q][r << 2]) = make_int4(aR0, aR1, aR2, aR3);
        __syncthreads();

        int AR = saccR[0][tid] + saccR[1][tid] + saccR[2][tid] + saccR[3][tid];
        float h  = sc2 * c2 + scr * (float)AR;
        float um = br * mr + h;
        mr = um * (1.f - (float)srj);
        int srn = (mr - thr) > 0.f ? 1 : 0;

        unsigned mskO = __ballot_sync(0xffffffffu, srn);
        if (lane == 0) cntO[wid] = __popc(mskO);
        __syncthreads();
        int offO = 0, nO = 0;
        #pragma unroll
        for (int w = 0; w < 16; w++) { int c = cntO[w]; if (w < wid) offO += c; nO += c; }
        if (srn) listO[offO + __popc(mskO & lmask)] = (unsigned short)tid;
        __syncthreads();

        int a3 = 0;
        for (int k = q; k < nO; k += 4) {
            int i = listO[k];
            a3 += (int)g_W3cm[i * 128 + r];
        }
        sacc3[q][r] = a3;
        __syncthreads();

        if (tid < 128) {
            int A3 = sacc3[0][tid] + sacc3[1][tid] + sacc3[2][tid] + sacc3[3][tid];
            m2 = b2 * m2 + sc3 * (float)A3;
            int s2 = (m2 - th2) > 0.f ? 1 : 0;
            if (s2) m2 = 0.f;
            out[((size_t)t * BB + b) * ON + tid] = (float)s2;
        }
        srj = srn;
        __syncthreads();
    }
}

// ---------------- launch ----------------
extern "C" void kernel_launch(void* const* d_in, const int* in_sizes, int n_in,
                              void* d_out, int out_size) {
    const float* data  = (const float*)d_in[0];
    const float* W1    = (const float*)d_in[1];
    const float* W2    = (const float*)d_in[2];
    const float* Wr    = (const float*)d_in[3];
    const float* W3    = (const float*)d_in[4];
    const float* beta1 = (const float*)d_in[5];
    const float* th1   = (const float*)d_in[6];
    const float* betar = (const float*)d_in[7];
    const float* thr   = (const float*)d_in[8];
    const float* beta2 = (const float*)d_in[9];
    const float* th2   = (const float*)d_in[10];
    float* out = (float*)d_out;

    k_zero<<<1, 32>>>();
    k_absmax<<<64, 256>>>(W1, 512 * 512, 0);
    k_absmax<<<64, 256>>>(W2, 512 * 512, 1);
    k_absmax<<<64, 256>>>(Wr, 512 * 512, 2);
    k_absmax<<<64, 256>>>(W3, 128 * 512, 3);
    k_scales<<<1, 4>>>();
    k_quantW1<<<512, 512>>>(W1);
    k_quantW2h<<<512, 512>>>(W2);
    k_quant_cm<<<512, 512>>>(Wr, 2);
    k_quant_cm<<<128, 512>>>(W3, 3);

    dim3 ggrid(512, 4);
    k_gemm1<<<ggrid, 256>>>(data);
    k_scan1<<<512, 256>>>(beta1, th1);
    dim3 g2(4, 512);
    k_gemm2_tc<<<g2, 256>>>();
    k_phaseB<<<256, 512>>>(betar, thr, beta2, th2, out);
}

// round 10
// speedup vs baseline: 1.6840x; 1.2501x over previous
#include <cuda_runtime.h>
#include <cuda_fp16.h>
#include <cstdint>

#define TT  256
#define BB  256
#define NIN 512
#define H1V 512
#define H2V 512
#define ON  128

// ---------------- device scratch (static, no allocation) ----------------
__device__ float        g_W1qT[NIN * H1V];          // [i][j] = fl(q*s) fp32 (transposed) - BIT-SENSITIVE
__device__ __half       g_W2h[H1V * H2V];           // [i][j] = q(W2[j,i]) exact int in fp16
__device__ signed char  g_Wrcm[H2V * H2V];          // [i][j] = q(Wrec[j,i])
__device__ __half       g_W3h[H2V * ON];            // [i][o] = q(W3[o,i]) exact int in fp16
__device__ float        g_scales[4];
__device__ unsigned int g_absmax[4];
__device__ float        g_cur1[(size_t)TT * BB * H1V];   // phase A currents, then C2, then C3
__device__ unsigned int g_s1w[TT * BB * 16];             // layer-1 spike bitmask
__device__ unsigned int g_srw[(size_t)BB * TT * 16];     // recurrent spike bitmask [b][t][16]

__device__ __forceinline__ float clip01(float x) { return fminf(fmaxf(x, 0.f), 1.f); }

__device__ __forceinline__ unsigned smem_u32(const void* p) {
    return (unsigned)__cvta_generic_to_shared(p);
}

// ---- packed fp32x2 helpers (SASS FFMA2; per-lane RN fp32, bit-identical) ----
__device__ __forceinline__ unsigned long long pk2(float lo, float hi) {
    unsigned long long r;
    asm("mov.b64 %0, {%1,%2};" : "=l"(r) : "f"(lo), "f"(hi));
    return r;
}
__device__ __forceinline__ void fma2(unsigned long long& d, unsigned long long a,
                                     unsigned long long b) {
    asm("fma.rn.f32x2 %0, %1, %2, %0;" : "+l"(d) : "l"(a), "l"(b));
}
__device__ __forceinline__ float2 upk2(unsigned long long v) {
    float2 f;
    asm("mov.b64 {%0,%1}, %2;" : "=f"(f.x), "=f"(f.y) : "l"(v));
    return f;
}

// ---- cp.async helpers ----
__device__ __forceinline__ void cpa16(unsigned smem, const void* g) {
    asm volatile("cp.async.cg.shared.global [%0], [%1], 16;" :: "r"(smem), "l"(g));
}
__device__ __forceinline__ void cpa_commit() { asm volatile("cp.async.commit_group;"); }
__device__ __forceinline__ void cpa_wait1() { asm volatile("cp.async.wait_group 1;"); }
__device__ __forceinline__ void cpa_wait0() { asm volatile("cp.async.wait_group 0;"); }

// ---- fp16 ldmatrix/mma helpers (validated in R5/R6: exact for integers) ----
__device__ __forceinline__ void ldmx4t(unsigned& r0, unsigned& r1, unsigned& r2, unsigned& r3,
                                       unsigned addr) {
    asm volatile("ldmatrix.sync.aligned.m8n8.x4.trans.shared.b16 {%0,%1,%2,%3}, [%4];"
                 : "=r"(r0), "=r"(r1), "=r"(r2), "=r"(r3) : "r"(addr));
}
__device__ __forceinline__ void mma16816(float* d, const unsigned* a, const unsigned* b) {
    asm volatile(
        "mma.sync.aligned.m16n8k16.row.col.f32.f16.f16.f32 "
        "{%0,%1,%2,%3}, {%4,%5,%6,%7}, {%8,%9}, {%0,%1,%2,%3};"
        : "+f"(d[0]), "+f"(d[1]), "+f"(d[2]), "+f"(d[3])
        : "r"(a[0]), "r"(a[1]), "r"(a[2]), "r"(a[3]), "r"(b[0]), "r"(b[1]));
}
__device__ __forceinline__ unsigned addrA(unsigned base, int lane, int k16, int col) {
    int g = lane >> 3, rig = lane & 7;
    int krow = k16 + ((g & 2) ? 8 : 0) + rig;
    int c    = col + ((g & 1) ? 8 : 0);
    return base + (unsigned)((krow * 136 + c) * 2);
}
__device__ __forceinline__ unsigned addrB(unsigned base, int lane, int k16, int col) {
    int g = lane >> 3, rig = lane & 7;
    int krow = k16 + ((g & 1) ? 8 : 0) + rig;
    int c    = col + ((g & 2) ? 8 : 0);
    return base + (unsigned)((krow * 136 + c) * 2);
}

// ---------------- quantization ----------------
__global__ void k_zero() {
    if (threadIdx.x < 4) g_absmax[threadIdx.x] = 0u;
}

__global__ void k_absmax4(const float* __restrict__ W1, const float* __restrict__ W2,
                          const float* __restrict__ Wr, const float* __restrict__ W3) {
    int slot = blockIdx.y;
    const float* src = (slot == 0) ? W1 : (slot == 1) ? W2 : (slot == 2) ? Wr : W3;
    int n = (slot == 3) ? 65536 : 262144;
    float v = 0.f;
    for (int i = blockIdx.x * blockDim.x + threadIdx.x; i < n; i += gridDim.x * blockDim.x)
        v = fmaxf(v, fabsf(src[i]));
    #pragma unroll
    for (int o = 16; o; o >>= 1) v = fmaxf(v, __shfl_xor_sync(0xffffffffu, v, o));
    __shared__ float sm[8];
    if ((threadIdx.x & 31) == 0) sm[threadIdx.x >> 5] = v;
    __syncthreads();
    if (threadIdx.x == 0) {
        float m = sm[0];
        #pragma unroll
        for (int w = 1; w < 8; w++) m = fmaxf(m, sm[w]);
        atomicMax(&g_absmax[slot], __float_as_uint(m));
    }
}

__global__ void k_scales() {
    if (threadIdx.x < 4)
        g_scales[threadIdx.x] = __uint_as_float(g_absmax[threadIdx.x]) / 127.0f;
}

// single merged quant pass; expressions identical to the validated R5 kernels
__global__ void k_quant_all(const float* __restrict__ W1, const float* __restrict__ W2,
                            const float* __restrict__ Wr, const float* __restrict__ W3) {
    int blk = blockIdx.x;
    if (blk < 512) {                                   // W1 -> fp32 fl(q*s), transposed
        int tid = blk * 512 + threadIdx.x;
        float s = g_scales[0];
        int i = tid >> 9, j = tid & 511;
        float w = W1[j * 512 + i];
        float q = fminf(fmaxf(rintf(w / s), -127.f), 127.f);
        g_W1qT[tid] = q * s;
    } else if (blk < 1024) {                           // W2 -> fp16 int, k-major
        int tid = (blk - 512) * 512 + threadIdx.x;
        float s = g_scales[1];
        int i = tid >> 9, j = tid & 511;
        float w = W2[j * 512 + i];
        float q = fminf(fmaxf(rintf(w / s), -127.f), 127.f);
        g_W2h[tid] = __float2half_rn(q);
    } else if (blk < 1536) {                           // Wrec -> int8 col-major
        int tid = (blk - 1024) * 512 + threadIdx.x;
        float s = g_scales[2];
        int i = tid >> 9, j = tid & 511;
        float w = Wr[j * 512 + i];
        float q = fminf(fmaxf(rintf(w / s), -127.f), 127.f);
        g_Wrcm[tid] = (signed char)(int)q;
    } else {                                           // W3 -> fp16 int, k-major [i][o]
        int tid = (blk - 1536) * 512 + threadIdx.x;    // 0..65535
        float s = g_scales[3];
        int i = tid >> 7, o = tid & 127;
        float w = W3[o * 512 + i];
        float q = fminf(fmaxf(rintf(w / s), -127.f), 127.f);
        g_W3h[tid] = __float2half_rn(q);
    }
}

// ---------------- layer-1 GEMM: bit-identical R5 FFMA2 chain + cp.async double buffer ----------------
__global__ __launch_bounds__(256, 2) void k_gemm1(const float* __restrict__ data) {
    __shared__ __align__(16) float As[2][16][128];
    __shared__ __align__(16) float Bs[2][16][128];
    const int lt = threadIdx.x;
    const int m0 = blockIdx.x << 7;
    const int n0 = blockIdx.y << 7;
    const int b  = m0 >> 8;
    const int tb = m0 & 255;
    const float* Ab = data + (size_t)b * (NIN * TT) + tb;   // A[mi,i] = Ab[i*256 + mi]
    const int tx = lt & 15, ty = lt >> 4;

    const unsigned baseA = smem_u32(&As[0][0][0]);
    const unsigned baseB = smem_u32(&Bs[0][0][0]);

    unsigned long long acc2[8][4];
    #pragma unroll
    for (int u = 0; u < 8; u++)
        #pragma unroll
        for (int vp = 0; vp < 4; vp++) acc2[u][vp] = 0ull;

    // issue async copies for tile k0 into buffer `bf`
    #define ISSUE_TILE(k0, bf)                                                        \
        {                                                                             \
            _Pragma("unroll")                                                         \
            for (int r = 0; r < 2; r++) {                                             \
                int c  = lt + (r << 8);                                               \
                int ki = c >> 5;                                                      \
                int c4 = (c & 31) << 2;                                               \
                unsigned so = (unsigned)(((bf) * 2048 + ki * 128 + c4) * 4);          \
                cpa16(baseA + so, Ab + ((k0) + ki) * TT + c4);                        \
                cpa16(baseB + so, g_W1qT + ((k0) + ki) * H1V + n0 + c4);              \
            }                                                                         \
            cpa_commit();                                                             \
        }

    ISSUE_TILE(0, 0);

    for (int k0 = 0; k0 < 512; k0 += 16) {
        const int buf = (k0 >> 4) & 1;
        if (k0 + 16 < 512) { ISSUE_TILE(k0 + 16, buf ^ 1); cpa_wait1(); }
        else               { cpa_wait0(); }
        __syncthreads();
        #pragma unroll
        for (int k = 0; k < 16; k++) {
            const float4* pa = reinterpret_cast<const float4*>(&As[buf][k][ty << 3]);
            const float4* pb = reinterpret_cast<const float4*>(&Bs[buf][k][tx << 3]);
            float4 a0 = pa[0], a1 = pa[1], b0 = pb[0], b1 = pb[1];
            float a[8] = {a0.x, a0.y, a0.z, a0.w, a1.x, a1.y, a1.z, a1.w};
            unsigned long long bp[4] = {pk2(b0.x, b0.y), pk2(b0.z, b0.w),
                                        pk2(b1.x, b1.y), pk2(b1.z, b1.w)};
            #pragma unroll
            for (int u = 0; u < 8; u++) {
                unsigned long long aa = pk2(a[u], a[u]);
                fma2(acc2[u][0], aa, bp[0]);
                fma2(acc2[u][1], aa, bp[1]);
                fma2(acc2[u][2], aa, bp[2]);
                fma2(acc2[u][3], aa, bp[3]);
            }
        }
        __syncthreads();
    }
    #pragma unroll
    for (int u = 0; u < 8; u++) {
        float2 e0 = upk2(acc2[u][0]), e1 = upk2(acc2[u][1]);
        float2 e2 = upk2(acc2[u][2]), e3 = upk2(acc2[u][3]);
        float* C = g_cur1 + (size_t)(m0 + (ty << 3) + u) * H1V + n0 + (tx << 3);
        reinterpret_cast<float4*>(C)[0] = make_float4(e0.x, e0.y, e1.x, e1.y);
        reinterpret_cast<float4*>(C)[1] = make_float4(e2.x, e2.y, e3.x, e3.y);
    }
    #undef ISSUE_TILE
}

// ---------------- layer-1 membrane scan -> spike bitmask (unchanged) ----------------
__global__ void k_scan1(const float* __restrict__ beta1p, const float* __restrict__ th1p) {
    int tid = blockIdx.x * blockDim.x + threadIdx.x;   // 131072
    int b = tid >> 9, j = tid & 511;
    float b1 = clip01(*beta1p);
    float th = *th1p;
    float m = 0.f;
    const float* cur = g_cur1 + (size_t)b * (256 * 512) + j;
    unsigned wslot = (unsigned)(j >> 5);
    unsigned* s1out = g_s1w + (size_t)b * (256 * 16) + wslot;
    for (int t = 0; t < 256; t++) {
        float c = cur[t * 512];
        m = b1 * m + c;
        bool s = (m - th) > 0.0f;
        if (s) m = 0.f;
        unsigned mask = __ballot_sync(0xffffffffu, s);
        if ((threadIdx.x & 31) == 0) s1out[t * 16] = mask;
    }
}

// ---------------- batched s1 @ W2^T (binary A, exact int accumulation on TC) ----------------
__global__ __launch_bounds__(256, 2) void k_gemm2_tc() {
    __shared__ __align__(16) __half Ahs[32 * 136];
    __shared__ __align__(16) __half Bh[32 * 136];
    __shared__ unsigned wbuf[128];
    const int tid = threadIdx.x, lane = tid & 31, wid = tid >> 5;
    const int wm = wid & 3, wn = wid >> 2;
    const int n0 = blockIdx.x << 7, m0 = blockIdx.y << 7;
    const int lk = tid >> 3;
    const int lm = (tid & 7) << 4;

    const unsigned baseA = smem_u32(&Ahs[0]);
    const unsigned baseB = smem_u32(&Bh[0]);

    float acc[2][8][4];
    #pragma unroll
    for (int mt = 0; mt < 2; mt++)
        #pragma unroll
        for (int nt = 0; nt < 8; nt++)
            #pragma unroll
            for (int e = 0; e < 4; e++) acc[mt][nt][e] = 0.f;

    const __half one = __float2half_rn(1.f);
    const __half zero = __float2half_rn(0.f);

    for (int k0 = 0; k0 < 512; k0 += 32) {
        __syncthreads();
        if (tid < 128)
            wbuf[tid] = g_s1w[(size_t)(m0 + tid) * 16 + (k0 >> 5)];
        {
            const __half* Bg = g_W2h + (size_t)(k0 + lk) * 512 + n0 + lm;
            *reinterpret_cast<int4*>(&Bh[lk * 136 + lm])     = *reinterpret_cast<const int4*>(Bg);
            *reinterpret_cast<int4*>(&Bh[lk * 136 + lm + 8]) = *reinterpret_cast<const int4*>(Bg + 8);
        }
        __syncthreads();
        #pragma unroll
        for (int i = 0; i < 8; i++) {
            int m = lm + 2 * i;
            unsigned w0 = wbuf[m], w1 = wbuf[m + 1];
            __half v0 = ((w0 >> lk) & 1u) ? one : zero;
            __half v1 = ((w1 >> lk) & 1u) ? one : zero;
            *reinterpret_cast<__half2*>(&Ahs[lk * 136 + m]) = __halves2half2(v0, v1);
        }
        __syncthreads();

        #pragma unroll
        for (int kk = 0; kk < 2; kk++) {
            const int k16 = kk * 16;
            unsigned bf[8][2];
            #pragma unroll
            for (int p = 0; p < 4; p++) {
                unsigned r0, r1, r2, r3;
                ldmx4t(r0, r1, r2, r3, addrB(baseB, lane, k16, wn * 64 + p * 16));
                bf[2 * p][0] = r0; bf[2 * p][1] = r1;
                bf[2 * p + 1][0] = r2; bf[2 * p + 1][1] = r3;
            }
            #pragma unroll
            for (int mt = 0; mt < 2; mt++) {
                unsigned a[4];
                ldmx4t(a[0], a[1], a[2], a[3], addrA(baseA, lane, k16, wm * 32 + mt * 16));
                #pragma unroll
                for (int nt = 0; nt < 8; nt++)
                    mma16816(acc[mt][nt], a, bf[nt]);
            }
        }
    }

    const int rr = lane >> 2, cq = (lane & 3) * 2;
    #pragma unroll
    for (int mt = 0; mt < 2; mt++) {
        #pragma unroll
        for (int nt = 0; nt < 8; nt++) {
            int row0 = m0 + wm * 32 + mt * 16 + rr;
            int col  = n0 + wn * 64 + nt * 8 + cq;
            float2 v0 = make_float2(acc[mt][nt][0], acc[mt][nt][1]);
            float2 v1 = make_float2(acc[mt][nt][2], acc[mt][nt][3]);
            *reinterpret_cast<float2*>(&g_cur1[(size_t)row0 * 512 + col])       = v0;
            *reinterpret_cast<float2*>(&g_cur1[(size_t)(row0 + 8) * 512 + col]) = v1;
        }
    }
}

// ---------------- recurrent layer only: one CTA per batch row, writes sr bitmasks ----------------
__global__ __launch_bounds__(512) void k_phaseB(
    const float* __restrict__ brp, const float* __restrict__ thrp)
{
    const int b    = blockIdx.x;
    const int tid  = threadIdx.x;
    const int q    = tid >> 7;
    const int r    = tid & 127;
    const int wid  = tid >> 5, lane = tid & 31;
    const unsigned lmask = (1u << lane) - 1u;

    __shared__ unsigned short listR[2][512];
    __shared__ int cntR[2][16];
    __shared__ int saccR[2][4][512];

    const float br  = clip01(*brp),  thr = *thrp;
    const float sc2 = g_scales[1], scr = g_scales[2];

    float mr = 0.f;
    int srj = 0;

    const float* c2p = g_cur1 + (size_t)b * (256 * 512);
    const int* Wri = reinterpret_cast<const int*>(g_Wrcm);
    unsigned* srw = g_srw + (size_t)b * (256 * 16);

    for (int t = 0; t < 256; t++) {
        const int d = t & 1;
        float c2 = c2p[(size_t)t * 512 + tid];   // exact integer value of s1 @ W2q^T

        unsigned mskR = __ballot_sync(0xffffffffu, srj);
        if (lane == 0) cntR[d][wid] = __popc(mskR);
        __syncthreads();

        int offR = 0, nR = 0;
        #pragma unroll
        for (int w = 0; w < 16; w++) {
            int cR = cntR[d][w];
            if (w < wid) offR += cR;
            nR += cR;
        }
        if (srj) listR[d][offR + __popc(mskR & lmask)] = (unsigned short)tid;
        __syncthreads();

        int aR0 = 0, aR1 = 0, aR2 = 0, aR3 = 0;
        for (int k = q; k < nR; k += 4) {
            int i = listR[d][k];
            int w = __ldg(Wri + i * 128 + r);
            aR0 += (int)(signed char)(w);
            aR1 += (int)(signed char)(w >> 8);
            aR2 += (int)(signed char)(w >> 16);
            aR3 += (w >> 24);
        }
        *reinterpret_cast<int4*>(&saccR[d][q][r << 2]) = make_int4(aR0, aR1, aR2, aR3);
        __syncthreads();

        int AR = saccR[d][0][tid] + saccR[d][1][tid] + saccR[d][2][tid] + saccR[d][3][tid];
        float h  = sc2 * c2 + scr * (float)AR;
        float um = br * mr + h;
        mr = um * (1.f - (float)srj);
        int srn = (mr - thr) > 0.f ? 1 : 0;

        unsigned mskO = __ballot_sync(0xffffffffu, srn);
        if (lane == 0) srw[t * 16 + wid] = mskO;
        srj = srn;
    }
}

// ---------------- batched sr @ W3^T (binary A, exact int accumulation on TC) ----------------
// C3[m][o] stored into g_cur1 (first 65536*128 floats)
__global__ __launch_bounds__(256, 2) void k_gemm3_tc() {
    __shared__ __align__(16) __half Ahs[32 * 136];
    __shared__ __align__(16) __half Bh[32 * 136];
    __shared__ unsigned wbuf[128];
    const int tid = threadIdx.x, lane = tid & 31, wid = tid >> 5;
    const int wm = wid & 3, wn = wid >> 2;
    const int m0 = blockIdx.x << 7;
    const int lk = tid >> 3;
    const int lm = (tid & 7) << 4;

    const unsigned baseA = smem_u32(&Ahs[0]);
    const unsigned baseB = smem_u32(&Bh[0]);

    float acc[2][8][4];
    #pragma unroll
    for (int mt = 0; mt < 2; mt++)
        #pragma unroll
        for (int nt = 0; nt < 8; nt++)
            #pragma unroll
            for (int e = 0; e < 4; e++) acc[mt][nt][e] = 0.f;

    const __half one = __float2half_rn(1.f);
    const __half zero = __float2half_rn(0.f);

    for (int k0 = 0; k0 < 512; k0 += 32) {
        __syncthreads();
        if (tid < 128)
            wbuf[tid] = g_srw[(size_t)(m0 + tid) * 16 + (k0 >> 5)];
        {
            const __half* Bg = g_W3h + (size_t)(k0 + lk) * 128 + lm;
            *reinterpret_cast<int4*>(&Bh[lk * 136 + lm])     = *reinterpret_cast<const int4*>(Bg);
            *reinterpret_cast<int4*>(&Bh[lk * 136 + lm + 8]) = *reinterpret_cast<const int4*>(Bg + 8);
        }
        __syncthreads();
        #pragma unroll
        for (int i = 0; i < 8; i++) {
            int m = lm + 2 * i;
            unsigned w0 = wbuf[m], w1 = wbuf[m + 1];
            __half v0 = ((w0 >> lk) & 1u) ? one : zero;
            __half v1 = ((w1 >> lk) & 1u) ? one : zero;
            *reinterpret_cast<__half2*>(&Ahs[lk * 136 + m]) = __halves2half2(v0, v1);
        }
        __syncthreads();

        #pragma unroll
        for (int kk = 0; kk < 2; kk++) {
            const int k16 = kk * 16;
            unsigned bf[8][2];
            #pragma unroll
            for (int p = 0; p < 4; p++) {
                unsigned r0, r1, r2, r3;
                ldmx4t(r0, r1, r2, r3, addrB(baseB, lane, k16, wn * 64 + p * 16));
                bf[2 * p][0] = r0; bf[2 * p][1] = r1;
                bf[2 * p + 1][0] = r2; bf[2 * p + 1][1] = r3;
            }
            #pragma unroll
            for (int mt = 0; mt < 2; mt++) {
                unsigned a[4];
                ldmx4t(a[0], a[1], a[2], a[3], addrA(baseA, lane, k16, wm * 32 + mt * 16));
                #pragma unroll
                for (int nt = 0; nt < 8; nt++)
                    mma16816(acc[mt][nt], a, bf[nt]);
            }
        }
    }

    const int rr = lane >> 2, cq = (lane & 3) * 2;
    #pragma unroll
    for (int mt = 0; mt < 2; mt++) {
        #pragma unroll
        for (int nt = 0; nt < 8; nt++) {
            int row0 = m0 + wm * 32 + mt * 16 + rr;
            int col  = wn * 64 + nt * 8 + cq;
            float2 v0 = make_float2(acc[mt][nt][0], acc[mt][nt][1]);
            float2 v1 = make_float2(acc[mt][nt][2], acc[mt][nt][3]);
            *reinterpret_cast<float2*>(&g_cur1[(size_t)row0 * 128 + col])       = v0;
            *reinterpret_cast<float2*>(&g_cur1[(size_t)(row0 + 8) * 128 + col]) = v1;
        }
    }
}

// ---------------- output membrane scan (expression identical to old phaseB m2 path) ----------------
__global__ void k_scan2(const float* __restrict__ b2p, const float* __restrict__ th2p,
                        float* __restrict__ out) {
    int gid = blockIdx.x * blockDim.x + threadIdx.x;   // 32768
    int b = gid >> 7, o = gid & 127;
    float b2 = clip01(*b2p), th2 = *th2p;
    float sc3 = g_scales[3];
    float m2 = 0.f;
    const float* c3 = g_cur1 + (size_t)(b << 8) * 128 + o;
    for (int t = 0; t < 256; t++) {
        float A3 = c3[t * 128];                        // exact integer sr @ W3q^T
        m2 = b2 * m2 + sc3 * A3;
        int s2 = (m2 - th2) > 0.f ? 1 : 0;
        if (s2) m2 = 0.f;
        out[((size_t)t * BB + b) * ON + o] = (float)s2;
    }
}

// ---------------- launch ----------------
extern "C" void kernel_launch(void* const* d_in, const int* in_sizes, int n_in,
                              void* d_out, int out_size) {
    const float* data  = (const float*)d_in[0];
    const float* W1    = (const float*)d_in[1];
    const float* W2    = (const float*)d_in[2];
    const float* Wr    = (const float*)d_in[3];
    const float* W3    = (const float*)d_in[4];
    const float* beta1 = (const float*)d_in[5];
    const float* th1   = (const float*)d_in[6];
    const float* betar = (const float*)d_in[7];
    const float* thr   = (const float*)d_in[8];
    const float* beta2 = (const float*)d_in[9];
    const float* th2   = (const float*)d_in[10];
    float* out = (float*)d_out;

    k_zero<<<1, 32>>>();
    k_absmax4<<<dim3(64, 4), 256>>>(W1, W2, Wr, W3);
    k_scales<<<1, 4>>>();
    k_quant_all<<<1664, 512>>>(W1, W2, Wr, W3);

    dim3 ggrid(512, 4);
    k_gemm1<<<ggrid, 256>>>(data);
    k_scan1<<<512, 256>>>(beta1, th1);
    dim3 g2(4, 512);
    k_gemm2_tc<<<g2, 256>>>();
    k_phaseB<<<256, 512>>>(betar, thr);
    k_gemm3_tc<<<512, 256>>>();
    k_scan2<<<64, 512>>>(beta2, th2, out);
}